// round 2
// baseline (speedup 1.0000x reference)
#include <cuda_runtime.h>
#include <cstdint>
#include <cstddef>

#define R_TOT 8192      // B*T
#define FIN   512
#define DD    128
#define CH    32        // chunk length
#define NCHUNK 256      // R_TOT/CH
#define NC_B  64        // chunks per batch
#define CLAMPV 1e20f

// ---------------- static device scratch (no cudaMalloc allowed) -------------
__device__ __align__(16) float gX [R_TOT * FIN];   // LayerNorm output
__device__ __align__(16) float gK [R_TOT * DD];
__device__ __align__(16) float gQ [R_TOT * DD];
__device__ __align__(16) float gV [R_TOT * DD];
__device__ __align__(16) float gSC[R_TOT * DD];    // x @ sc_w
__device__ __align__(16) float gP [R_TOT * DD];    // attention out (pre-FF)
__device__ __align__(16) float gH [R_TOT * DD];    // FF hidden
__device__ __align__(16) float gSprev[NCHUNK * DD * DD]; // chunk sums -> excl. prefix (+S0)
__device__ __align__(16) float gZprev[NCHUNK * DD];      // same for Z (+Z0)

typedef unsigned long long u64;

// ---------------- packed f32x2 helpers --------------------------------------
__device__ __forceinline__ u64 pk2(float lo, float hi) {
    u64 r; asm("mov.b64 %0, {%1, %2};" : "=l"(r) : "f"(lo), "f"(hi)); return r;
}
__device__ __forceinline__ u64 pkdup(float v) {
    u64 r; asm("mov.b64 %0, {%1, %1};" : "=l"(r) : "f"(v)); return r;
}
__device__ __forceinline__ void fma2(u64& d, u64 a, u64 b) {
    asm("fma.rn.f32x2 %0, %1, %2, %0;" : "+l"(d) : "l"(a), "l"(b));
}
__device__ __forceinline__ float2 upk2(u64 v) {
    float lo, hi; asm("mov.b64 {%0, %1}, %2;" : "=f"(lo), "=f"(hi) : "l"(v));
    return make_float2(lo, hi);
}
__device__ __forceinline__ float phif(float z) { return z > 0.f ? z + 1.f : expf(z); }
__device__ __forceinline__ float clampv(float v) { return fminf(fmaxf(v, -CLAMPV), CLAMPV); }

// ---------------- 1) LayerNorm over Fin=512 ---------------------------------
__global__ __launch_bounds__(128) void ln_kernel(const float* __restrict__ h,
                                                 const float* __restrict__ gam,
                                                 const float* __restrict__ bet) {
    int row = blockIdx.x;
    int t = threadIdx.x;                           // 4 features each
    const float4* hr = reinterpret_cast<const float4*>(h + (size_t)row * FIN);
    float4 v = hr[t];
    float s = v.x + v.y + v.z + v.w;
    float s2 = v.x * v.x + v.y * v.y + v.z * v.z + v.w * v.w;
#pragma unroll
    for (int o = 16; o > 0; o >>= 1) {
        s  += __shfl_xor_sync(0xffffffffu, s,  o);
        s2 += __shfl_xor_sync(0xffffffffu, s2, o);
    }
    __shared__ float rs[4], rs2[4], bc[2];
    if ((t & 31) == 0) { rs[t >> 5] = s; rs2[t >> 5] = s2; }
    __syncthreads();
    if (t == 0) {
        float ss  = rs[0] + rs[1] + rs[2] + rs[3];
        float ss2 = rs2[0] + rs2[1] + rs2[2] + rs2[3];
        float mu  = ss * (1.0f / FIN);
        float var = ss2 * (1.0f / FIN) - mu * mu;
        bc[0] = mu;
        bc[1] = rsqrtf(var + 1e-5f);
    }
    __syncthreads();
    float mu = bc[0], rstd = bc[1];
    float4 g4 = reinterpret_cast<const float4*>(gam)[t];
    float4 b4 = reinterpret_cast<const float4*>(bet)[t];
    float4 o;
    o.x = (v.x - mu) * rstd * g4.x + b4.x;
    o.y = (v.y - mu) * rstd * g4.y + b4.y;
    o.z = (v.z - mu) * rstd * g4.z + b4.z;
    o.w = (v.w - mu) * rstd * g4.w + b4.w;
    reinterpret_cast<float4*>(gX + (size_t)row * FIN)[t] = o;
}

// ---------------- 2) Generic [8192,K]@[K,128] GEMM via FFMA2 ----------------
// EPI: 0 = phi(elu+1), 1 = none, 2 = relu(.+bias), 3 = relu(.+bias)+res+resb
// gridDim.y selects (W0,C0) vs (W1,C1). Tile: 64 rows x 128 cols, 256 threads.
template<int EPI>
__global__ __launch_bounds__(256) void gemm_kernel(
    const float* __restrict__ A,
    const float* __restrict__ W0, const float* __restrict__ W1,
    float* __restrict__ C0, float* __restrict__ C1, int K,
    const float* __restrict__ bias,
    const float* __restrict__ res, const float* __restrict__ resb)
{
    const float* W = blockIdx.y ? W1 : W0;
    float* C = blockIdx.y ? C1 : C0;
    __shared__ float As[16][68];    // transposed A tile (stride 68 -> 16B-aligned rows)
    __shared__ float Ws[16][DD];

    int tid = threadIdx.x;
    int m0 = blockIdx.x * 64;
    int r0 = (tid >> 4) * 4;        // 4 rows
    int c0 = (tid & 15) * 8;        // 8 cols
    u64 acc[4][4];
#pragma unroll
    for (int i = 0; i < 4; i++)
#pragma unroll
        for (int j = 0; j < 4; j++) acc[i][j] = 0ull;

    int lrow = tid >> 2;            // A loader: 64 rows x 16 k
    int lk   = (tid & 3) * 4;
    int wrow = tid >> 4;            // W loader: 16 rows x 128 cols
    int wcol = (tid & 15) * 8;

    for (int k0 = 0; k0 < K; k0 += 16) {
        float4 av  = *(const float4*)(A + (size_t)(m0 + lrow) * K + k0 + lk);
        float4 wv0 = *(const float4*)(W + (size_t)(k0 + wrow) * DD + wcol);
        float4 wv1 = *(const float4*)(W + (size_t)(k0 + wrow) * DD + wcol + 4);
        __syncthreads();
        As[lk + 0][lrow] = av.x; As[lk + 1][lrow] = av.y;
        As[lk + 2][lrow] = av.z; As[lk + 3][lrow] = av.w;
        *(float4*)&Ws[wrow][wcol]     = wv0;
        *(float4*)&Ws[wrow][wcol + 4] = wv1;
        __syncthreads();
#pragma unroll
        for (int kk = 0; kk < 16; kk++) {
            float4 a4 = *(const float4*)&As[kk][r0];
            ulonglong2 b01 = *(const ulonglong2*)&Ws[kk][c0];
            ulonglong2 b23 = *(const ulonglong2*)&Ws[kk][c0 + 4];
            float ar[4] = {a4.x, a4.y, a4.z, a4.w};
#pragma unroll
            for (int i = 0; i < 4; i++) {
                u64 aa = pkdup(ar[i]);
                fma2(acc[i][0], aa, b01.x);
                fma2(acc[i][1], aa, b01.y);
                fma2(acc[i][2], aa, b23.x);
                fma2(acc[i][3], aa, b23.y);
            }
        }
    }

    float bb[8], rb[8];
    if (EPI >= 2) {
        float4 t0 = *(const float4*)&bias[c0], t1 = *(const float4*)&bias[c0 + 4];
        bb[0]=t0.x; bb[1]=t0.y; bb[2]=t0.z; bb[3]=t0.w;
        bb[4]=t1.x; bb[5]=t1.y; bb[6]=t1.z; bb[7]=t1.w;
    }
    if (EPI == 3) {
        float4 t0 = *(const float4*)&resb[c0], t1 = *(const float4*)&resb[c0 + 4];
        rb[0]=t0.x; rb[1]=t0.y; rb[2]=t0.z; rb[3]=t0.w;
        rb[4]=t1.x; rb[5]=t1.y; rb[6]=t1.z; rb[7]=t1.w;
    }
#pragma unroll
    for (int i = 0; i < 4; i++) {
        int row = m0 + r0 + i;
        float v[8];
#pragma unroll
        for (int j = 0; j < 4; j++) {
            float2 f = upk2(acc[i][j]);
            v[2 * j] = f.x; v[2 * j + 1] = f.y;
        }
        if (EPI == 0) {
#pragma unroll
            for (int x = 0; x < 8; x++) v[x] = phif(v[x]);
        } else if (EPI == 2) {
#pragma unroll
            for (int x = 0; x < 8; x++) v[x] = fmaxf(v[x] + bb[x], 0.f);
        } else if (EPI == 3) {
            float4 q0 = *(const float4*)&res[(size_t)row * DD + c0];
            float4 q1 = *(const float4*)&res[(size_t)row * DD + c0 + 4];
            float rr[8] = {q0.x,q0.y,q0.z,q0.w,q1.x,q1.y,q1.z,q1.w};
#pragma unroll
            for (int x = 0; x < 8; x++) v[x] = fmaxf(v[x] + bb[x], 0.f) + rr[x] + rb[x];
        }
        *(float4*)(C + (size_t)row * DD + c0)     = make_float4(v[0], v[1], v[2], v[3]);
        *(float4*)(C + (size_t)row * DD + c0 + 4) = make_float4(v[4], v[5], v[6], v[7]);
    }
}

// ---------------- 3) per-chunk KV outer-product sums + K sums ---------------
__global__ __launch_bounds__(512) void chunksum_kernel() {
    __shared__ float sK[CH][DD];
    __shared__ float sV[CH][DD];
    int tid = threadIdx.x;
    int chunk = blockIdx.x;
    int base = chunk * CH;
    int lr = tid >> 4, lc = (tid & 15) * 8;
    *(float4*)&sK[lr][lc]     = *(const float4*)&gK[(size_t)(base + lr) * DD + lc];
    *(float4*)&sK[lr][lc + 4] = *(const float4*)&gK[(size_t)(base + lr) * DD + lc + 4];
    *(float4*)&sV[lr][lc]     = *(const float4*)&gV[(size_t)(base + lr) * DD + lc];
    *(float4*)&sV[lr][lc + 4] = *(const float4*)&gV[(size_t)(base + lr) * DD + lc + 4];
    __syncthreads();

    int r0 = (tid >> 4) * 4;   // 4 rows (K index)
    int c0 = (tid & 15) * 8;   // 8 cols (V index)
    u64 acc[4][4];
#pragma unroll
    for (int i = 0; i < 4; i++)
#pragma unroll
        for (int j = 0; j < 4; j++) acc[i][j] = 0ull;

#pragma unroll 4
    for (int t = 0; t < CH; t++) {
        float4 kv = *(const float4*)&sK[t][r0];
        ulonglong2 v01 = *(const ulonglong2*)&sV[t][c0];
        ulonglong2 v23 = *(const ulonglong2*)&sV[t][c0 + 4];
        float kr[4] = {kv.x, kv.y, kv.z, kv.w};
#pragma unroll
        for (int i = 0; i < 4; i++) {
            u64 aa = pkdup(kr[i]);
            fma2(acc[i][0], aa, v01.x);
            fma2(acc[i][1], aa, v01.y);
            fma2(acc[i][2], aa, v23.x);
            fma2(acc[i][3], aa, v23.y);
        }
    }
    float* dst = gSprev + (size_t)chunk * DD * DD;
#pragma unroll
    for (int i = 0; i < 4; i++) {
        float2 f0 = upk2(acc[i][0]), f1 = upk2(acc[i][1]);
        float2 f2 = upk2(acc[i][2]), f3 = upk2(acc[i][3]);
        *(float4*)&dst[(r0 + i) * DD + c0]     = make_float4(f0.x, f0.y, f1.x, f1.y);
        *(float4*)&dst[(r0 + i) * DD + c0 + 4] = make_float4(f2.x, f2.y, f3.x, f3.y);
    }
    if (tid < DD) {
        float s = 0.f;
#pragma unroll 8
        for (int t = 0; t < CH; t++) s += sK[t][tid];
        gZprev[chunk * DD + tid] = s;
    }
}

// ---------------- 4) exclusive inter-chunk scans (fold S0 / Z0 in) ----------
__global__ __launch_bounds__(256) void scanS_kernel(const float* __restrict__ S0) {
    int e = blockIdx.x * 256 + threadIdx.x;        // 0..16383
    int b = blockIdx.y;
    float run = S0[(size_t)b * 16384 + e];
#pragma unroll 4
    for (int c = 0; c < NC_B; c++) {
        size_t idx = ((size_t)(b * NC_B + c)) * 16384 + e;
        float v = gSprev[idx];
        gSprev[idx] = run;
        run += v;
    }
}
__global__ __launch_bounds__(128) void scanZ_kernel(const float* __restrict__ Z0) {
    int d = threadIdx.x;
    int b = blockIdx.x;
    float run = Z0[b * DD + d];
#pragma unroll 4
    for (int c = 0; c < NC_B; c++) {
        size_t idx = (size_t)(b * NC_B + c) * DD + d;
        float v = gZprev[idx];
        gZprev[idx] = run;
        run += v;
    }
}

// ---------------- 5) S output: stream running state to HBM ------------------
__global__ __launch_bounds__(512) void swrite_kernel(float* __restrict__ Sout) {
    __shared__ float sK[CH][DD];
    __shared__ float sV[CH][DD];
    int tid = threadIdx.x;
    int chunk = blockIdx.x;
    int base = chunk * CH;
    int lr = tid >> 4, lc = (tid & 15) * 8;
    *(float4*)&sK[lr][lc]     = *(const float4*)&gK[(size_t)(base + lr) * DD + lc];
    *(float4*)&sK[lr][lc + 4] = *(const float4*)&gK[(size_t)(base + lr) * DD + lc + 4];
    *(float4*)&sV[lr][lc]     = *(const float4*)&gV[(size_t)(base + lr) * DD + lc];
    *(float4*)&sV[lr][lc + 4] = *(const float4*)&gV[(size_t)(base + lr) * DD + lc + 4];

    int r0 = (tid >> 4) * 4;
    int c0 = (tid & 15) * 8;
    const float* Sp = gSprev + (size_t)chunk * DD * DD;
    u64 acc[4][4];
#pragma unroll
    for (int i = 0; i < 4; i++) {
        float4 f0 = *(const float4*)&Sp[(r0 + i) * DD + c0];
        float4 f1 = *(const float4*)&Sp[(r0 + i) * DD + c0 + 4];
        acc[i][0] = pk2(f0.x, f0.y); acc[i][1] = pk2(f0.z, f0.w);
        acc[i][2] = pk2(f1.x, f1.y); acc[i][3] = pk2(f1.z, f1.w);
    }
    __syncthreads();

    for (int t = 0; t < CH; t++) {
        float4 kv = *(const float4*)&sK[t][r0];
        ulonglong2 v01 = *(const ulonglong2*)&sV[t][c0];
        ulonglong2 v23 = *(const ulonglong2*)&sV[t][c0 + 4];
        float kr[4] = {kv.x, kv.y, kv.z, kv.w};
        float* drow = Sout + (size_t)(base + t) * 16384;
#pragma unroll
        for (int i = 0; i < 4; i++) {
            u64 aa = pkdup(kr[i]);
            fma2(acc[i][0], aa, v01.x);
            fma2(acc[i][1], aa, v01.y);
            fma2(acc[i][2], aa, v23.x);
            fma2(acc[i][3], aa, v23.y);
            float2 f0 = upk2(acc[i][0]), f1 = upk2(acc[i][1]);
            float2 f2 = upk2(acc[i][2]), f3 = upk2(acc[i][3]);
            *(float4*)&drow[(r0 + i) * DD + c0] =
                make_float4(clampv(f0.x), clampv(f0.y), clampv(f1.x), clampv(f1.y));
            *(float4*)&drow[(r0 + i) * DD + c0 + 4] =
                make_float4(clampv(f2.x), clampv(f2.y), clampv(f3.x), clampv(f3.y));
        }
    }
}

// ---------------- 6) attention output + Z output -----------------------------
__global__ __launch_bounds__(256) void attn_kernel(float* __restrict__ Zout) {
    __shared__ float sQ[CH][DD];        // 16KB
    __shared__ float sKV[CH][DD];       // 16KB: K first, later V
    __shared__ float sA[CH][CH + 2];    // masked QK^T
    __shared__ float sSp[16][DD];       // Sprev tile
    __shared__ float sRow[CH];          // denominators
    __shared__ float zp[DD];            // Zprev (+Z0)

    int tid = threadIdx.x;
    int chunk = blockIdx.x;
    int base = chunk * CH;
    int lr = tid >> 3, lc = (tid & 7) * 16;
#pragma unroll
    for (int j = 0; j < 4; j++) {
        *(float4*)&sQ[lr][lc + 4 * j]  = *(const float4*)&gQ[(size_t)(base + lr) * DD + lc + 4 * j];
        *(float4*)&sKV[lr][lc + 4 * j] = *(const float4*)&gK[(size_t)(base + lr) * DD + lc + 4 * j];
    }
    if (tid < DD) zp[tid] = gZprev[chunk * DD + tid];
    __syncthreads();

    // Phase A: A[t][t'] = Q_t . K_t'  (masked t' <= t)
    {
        int q0 = (tid >> 4) * 2;
        int k0c = (tid & 15) * 2;
        u64 a2[2][2] = {{0ull, 0ull}, {0ull, 0ull}};
#pragma unroll 8
        for (int dd = 0; dd < 64; dd++) {
            u64 qp0 = *(const u64*)&sQ[q0][2 * dd];
            u64 qp1 = *(const u64*)&sQ[q0 + 1][2 * dd];
            u64 kp0 = *(const u64*)&sKV[k0c][2 * dd];
            u64 kp1 = *(const u64*)&sKV[k0c + 1][2 * dd];
            fma2(a2[0][0], qp0, kp0); fma2(a2[0][1], qp0, kp1);
            fma2(a2[1][0], qp1, kp0); fma2(a2[1][1], qp1, kp1);
        }
#pragma unroll
        for (int i = 0; i < 2; i++)
#pragma unroll
            for (int j = 0; j < 2; j++) {
                float2 f = upk2(a2[i][j]);
                int tq = q0 + i, tk = k0c + j;
                sA[tq][tk] = (tk <= tq) ? (f.x + f.y) : 0.0f;
            }
    }

    // Z output (uses sKV = K, before overwrite)
    if (tid < DD) {
        float zacc = zp[tid];
        for (int t = 0; t < CH; t++) {
            zacc += sKV[t][tid];
            Zout[(size_t)(base + t) * DD + tid] = clampv(zacc);
        }
    }
    __syncthreads();

    // denominators: rowsum(masked A) + Q_t . Zprev + eps
    if (tid < CH) {
        float s = 1e-5f;
#pragma unroll 8
        for (int c = 0; c < CH; c++) s += sA[tid][c];
        float qz = 0.f;
#pragma unroll 8
        for (int d = 0; d < DD; d++) qz += sQ[tid][d] * zp[d];
        sRow[tid] = s + qz;
    }
    __syncthreads();

    // overwrite sKV with V
#pragma unroll
    for (int j = 0; j < 4; j++)
        *(float4*)&sKV[lr][lc + 4 * j] = *(const float4*)&gV[(size_t)(base + lr) * DD + lc + 4 * j];

    int r0 = (tid >> 4) * 2;     // 2 rows
    int c0 = (tid & 15) * 8;     // 8 cols
    u64 acc[2][4] = {{0ull,0ull,0ull,0ull},{0ull,0ull,0ull,0ull}};

    // Phase C: Q @ (Sprev + S0)  -- 8 tiles of 16 d's
    const float* Sp = gSprev + (size_t)chunk * DD * DD;
    int spr = tid >> 4, spc = (tid & 15) * 8;
    for (int dt = 0; dt < 8; dt++) {
        __syncthreads();
        *(float4*)&sSp[spr][spc]     = *(const float4*)&Sp[(dt * 16 + spr) * DD + spc];
        *(float4*)&sSp[spr][spc + 4] = *(const float4*)&Sp[(dt * 16 + spr) * DD + spc + 4];
        __syncthreads();
#pragma unroll
        for (int d = 0; d < 16; d++) {
            u64 aa0 = pkdup(sQ[r0][dt * 16 + d]);
            u64 aa1 = pkdup(sQ[r0 + 1][dt * 16 + d]);
            ulonglong2 s01 = *(const ulonglong2*)&sSp[d][c0];
            ulonglong2 s23 = *(const ulonglong2*)&sSp[d][c0 + 4];
            fma2(acc[0][0], aa0, s01.x); fma2(acc[0][1], aa0, s01.y);
            fma2(acc[0][2], aa0, s23.x); fma2(acc[0][3], aa0, s23.y);
            fma2(acc[1][0], aa1, s01.x); fma2(acc[1][1], aa1, s01.y);
            fma2(acc[1][2], aa1, s23.x); fma2(acc[1][3], aa1, s23.y);
        }
    }
    __syncthreads();   // V visible (also covered by loop syncs)

    // Phase B: masked A @ V (intra-chunk causal part)
#pragma unroll 4
    for (int t = 0; t < CH; t++) {
        u64 aa0 = pkdup(sA[r0][t]);
        u64 aa1 = pkdup(sA[r0 + 1][t]);
        ulonglong2 v01 = *(const ulonglong2*)&sKV[t][c0];
        ulonglong2 v23 = *(const ulonglong2*)&sKV[t][c0 + 4];
        fma2(acc[0][0], aa0, v01.x); fma2(acc[0][1], aa0, v01.y);
        fma2(acc[0][2], aa0, v23.x); fma2(acc[0][3], aa0, v23.y);
        fma2(acc[1][0], aa1, v01.x); fma2(acc[1][1], aa1, v01.y);
        fma2(acc[1][2], aa1, v23.x); fma2(acc[1][3], aa1, v23.y);
    }

    // divide and store P
#pragma unroll
    for (int i = 0; i < 2; i++) {
        float rd = 1.0f / sRow[r0 + i];
        float2 f0 = upk2(acc[i][0]), f1 = upk2(acc[i][1]);
        float2 f2 = upk2(acc[i][2]), f3 = upk2(acc[i][3]);
        float* dst = gP + (size_t)(base + r0 + i) * DD + c0;
        *(float4*)dst       = make_float4(f0.x * rd, f0.y * rd, f1.x * rd, f1.y * rd);
        *(float4*)(dst + 4) = make_float4(f2.x * rd, f2.y * rd, f3.x * rd, f3.y * rd);
    }
}

// ---------------- launch ------------------------------------------------------
extern "C" void kernel_launch(void* const* d_in, const int* in_sizes, int n_in,
                              void* d_out, int out_size) {
    const float* history = (const float*)d_in[0];
    const float* S0   = (const float*)d_in[1];
    const float* Z0   = (const float*)d_in[2];
    const float* Wk   = (const float*)d_in[3];
    const float* Wq   = (const float*)d_in[4];
    const float* Wv   = (const float*)d_in[5];
    const float* ln_g = (const float*)d_in[6];
    const float* ln_b = (const float*)d_in[7];
    const float* w1   = (const float*)d_in[8];
    const float* b1   = (const float*)d_in[9];
    const float* w2   = (const float*)d_in[10];
    const float* b2   = (const float*)d_in[11];
    const float* sc_w = (const float*)d_in[12];
    const float* sc_b = (const float*)d_in[13];

    float* outO = (float*)d_out;                            // [8192,128]
    float* outS = outO + (size_t)R_TOT * DD;                // [8192,128,128]
    float* outZ = outS + (size_t)R_TOT * DD * DD;           // [8192,128]

    float *pX, *pK, *pQ, *pV, *pSC, *pP, *pH;
    cudaGetSymbolAddress((void**)&pX,  gX);
    cudaGetSymbolAddress((void**)&pK,  gK);
    cudaGetSymbolAddress((void**)&pQ,  gQ);
    cudaGetSymbolAddress((void**)&pV,  gV);
    cudaGetSymbolAddress((void**)&pSC, gSC);
    cudaGetSymbolAddress((void**)&pP,  gP);
    cudaGetSymbolAddress((void**)&pH,  gH);

    // 1) LayerNorm
    ln_kernel<<<R_TOT, 128>>>(history, ln_g, ln_b);
    // 2) projections: K,Q with phi; V, shortcut plain
    gemm_kernel<0><<<dim3(128, 2), 256>>>(pX, Wk, Wq, pK, pQ, FIN, nullptr, nullptr, nullptr);
    gemm_kernel<1><<<dim3(128, 2), 256>>>(pX, Wv, sc_w, pV, pSC, FIN, nullptr, nullptr, nullptr);
    // 3) chunk sums, 4) scans
    chunksum_kernel<<<NCHUNK, 512>>>();
    scanS_kernel<<<dim3(64, 4), 256>>>(S0);
    scanZ_kernel<<<4, 128>>>(Z0);
    // 5) S output stream
    swrite_kernel<<<NCHUNK, 512>>>(outS);
    // 6) attention output + Z output
    attn_kernel<<<NCHUNK, 256>>>(outZ);
    // 7) FF + residual
    gemm_kernel<2><<<dim3(128, 1), 256>>>(pP, w1, w1, pH, pH, DD, b1, nullptr, nullptr);
    gemm_kernel<3><<<dim3(128, 1), 256>>>(pH, w2, w2, outO, outO, DD, b2, pSC, sc_b);
}

// round 3
// speedup vs baseline: 1.2908x; 1.2908x over previous
#include <cuda_runtime.h>
#include <cstdint>
#include <cstddef>

#define R_TOT 8192      // B*T
#define FIN   512
#define DD    128
#define CH    32        // chunk length
#define NCHUNK 256      // R_TOT/CH
#define NC_B  64        // chunks per batch

// ---------------- static device scratch (no cudaMalloc allowed) -------------
__device__ __align__(16) float gX [R_TOT * FIN];
__device__ __align__(16) float gK [R_TOT * DD];
__device__ __align__(16) float gQ [R_TOT * DD];
__device__ __align__(16) float gV [R_TOT * DD];
__device__ __align__(16) float gSC[R_TOT * DD];
__device__ __align__(16) float gP [R_TOT * DD];
__device__ __align__(16) float gH [R_TOT * DD];
__device__ __align__(16) float gSprev[NCHUNK * DD * DD];
__device__ __align__(16) float gZprev[NCHUNK * DD];

typedef unsigned long long u64;

__device__ __forceinline__ u64 pkdup(float v) {
    u64 r; asm("mov.b64 %0, {%1, %1};" : "=l"(r) : "f"(v)); return r;
}
__device__ __forceinline__ void fma2(u64& d, u64 a, u64 b) {
    asm("fma.rn.f32x2 %0, %1, %2, %0;" : "+l"(d) : "l"(a), "l"(b));
}
__device__ __forceinline__ float2 upk2(u64 v) {
    float lo, hi; asm("mov.b64 {%0, %1}, %2;" : "=f"(lo), "=f"(hi) : "l"(v));
    return make_float2(lo, hi);
}
__device__ __forceinline__ u64 pk2(float lo, float hi) {
    u64 r; asm("mov.b64 %0, {%1, %2};" : "=l"(r) : "f"(lo), "f"(hi)); return r;
}
__device__ __forceinline__ float phif(float z) { return z > 0.f ? z + 1.f : expf(z); }

// ---------------- 1) LayerNorm over Fin=512 ---------------------------------
__global__ __launch_bounds__(128) void ln_kernel(const float* __restrict__ h,
                                                 const float* __restrict__ gam,
                                                 const float* __restrict__ bet) {
    int row = blockIdx.x;
    int t = threadIdx.x;
    const float4* hr = reinterpret_cast<const float4*>(h + (size_t)row * FIN);
    float4 v = hr[t];
    float s = v.x + v.y + v.z + v.w;
    float s2 = v.x * v.x + v.y * v.y + v.z * v.z + v.w * v.w;
#pragma unroll
    for (int o = 16; o > 0; o >>= 1) {
        s  += __shfl_xor_sync(0xffffffffu, s,  o);
        s2 += __shfl_xor_sync(0xffffffffu, s2, o);
    }
    __shared__ float rs[4], rs2[4], bc[2];
    if ((t & 31) == 0) { rs[t >> 5] = s; rs2[t >> 5] = s2; }
    __syncthreads();
    if (t == 0) {
        float ss  = rs[0] + rs[1] + rs[2] + rs[3];
        float ss2 = rs2[0] + rs2[1] + rs2[2] + rs2[3];
        float mu  = ss * (1.0f / FIN);
        float var = ss2 * (1.0f / FIN) - mu * mu;
        bc[0] = mu; bc[1] = rsqrtf(var + 1e-5f);
    }
    __syncthreads();
    float mu = bc[0], rstd = bc[1];
    float4 g4 = reinterpret_cast<const float4*>(gam)[t];
    float4 b4 = reinterpret_cast<const float4*>(bet)[t];
    float4 o;
    o.x = (v.x - mu) * rstd * g4.x + b4.x;
    o.y = (v.y - mu) * rstd * g4.y + b4.y;
    o.z = (v.z - mu) * rstd * g4.z + b4.z;
    o.w = (v.w - mu) * rstd * g4.w + b4.w;
    reinterpret_cast<float4*>(gX + (size_t)row * FIN)[t] = o;
}

// ---------------- 2) 128x128-tile GEMM, 8x8/thread, FFMA2, prefetch ---------
// MODE 0: projections, W/C selected by blockIdx.y, phi for y<2
// MODE 1: FF1  relu(x+bias)
// MODE 2: FF2  relu(x+bias) + res + resb
template<int KSIZE, int MODE>
__global__ __launch_bounds__(256) void gemm_kernel(
    const float* __restrict__ A,
    const float* __restrict__ W0, const float* __restrict__ W1,
    const float* __restrict__ W2, const float* __restrict__ W3,
    float* __restrict__ C0, float* __restrict__ C1,
    float* __restrict__ C2, float* __restrict__ C3,
    const float* __restrict__ bias,
    const float* __restrict__ res, const float* __restrict__ resb)
{
    __shared__ float As[16][132];
    __shared__ float Ws[16][132];

    const float* W = W0; float* C = C0;
    bool dophi = false;
    if (MODE == 0) {
        int y = blockIdx.y;
        W = (y == 0) ? W0 : (y == 1) ? W1 : (y == 2) ? W2 : W3;
        C = (y == 0) ? C0 : (y == 1) ? C1 : (y == 2) ? C2 : C3;
        dophi = (y < 2);
    }

    int tid = threadIdx.x;
    int m0 = blockIdx.x * 128;
    int lrow = tid >> 1, lk = (tid & 1) * 8;
    int wrow = tid >> 4, wcol = (tid & 15) * 8;
    int r0 = (tid >> 4) * 8, c0 = (tid & 15) * 8;

    u64 acc[8][4];
#pragma unroll
    for (int i = 0; i < 8; i++)
#pragma unroll
        for (int j = 0; j < 4; j++) acc[i][j] = 0ull;

    const float* aptr = A + (size_t)(m0 + lrow) * KSIZE + lk;
    const float* wptr = W + (size_t)wrow * DD + wcol;

    float4 a0 = *(const float4*)(aptr);
    float4 a1 = *(const float4*)(aptr + 4);
    float4 w0 = *(const float4*)(wptr);
    float4 w1 = *(const float4*)(wptr + 4);

    for (int k0 = 0; k0 < KSIZE; k0 += 16) {
        __syncthreads();
        As[lk + 0][lrow] = a0.x; As[lk + 1][lrow] = a0.y;
        As[lk + 2][lrow] = a0.z; As[lk + 3][lrow] = a0.w;
        As[lk + 4][lrow] = a1.x; As[lk + 5][lrow] = a1.y;
        As[lk + 6][lrow] = a1.z; As[lk + 7][lrow] = a1.w;
        *(float4*)&Ws[wrow][wcol]     = w0;
        *(float4*)&Ws[wrow][wcol + 4] = w1;
        __syncthreads();
        if (k0 + 16 < KSIZE) {
            a0 = *(const float4*)(aptr + k0 + 16);
            a1 = *(const float4*)(aptr + k0 + 20);
            w0 = *(const float4*)(wptr + (size_t)(k0 + 16) * DD);
            w1 = *(const float4*)(wptr + (size_t)(k0 + 16) * DD + 4);
        }
#pragma unroll
        for (int kk = 0; kk < 16; kk++) {
            float4 af0 = *(const float4*)&As[kk][r0];
            float4 af1 = *(const float4*)&As[kk][r0 + 4];
            ulonglong2 b01 = *(const ulonglong2*)&Ws[kk][c0];
            ulonglong2 b23 = *(const ulonglong2*)&Ws[kk][c0 + 4];
            float ar[8] = {af0.x, af0.y, af0.z, af0.w, af1.x, af1.y, af1.z, af1.w};
#pragma unroll
            for (int i = 0; i < 8; i++) {
                u64 aa = pkdup(ar[i]);
                fma2(acc[i][0], aa, b01.x);
                fma2(acc[i][1], aa, b01.y);
                fma2(acc[i][2], aa, b23.x);
                fma2(acc[i][3], aa, b23.y);
            }
        }
    }

    float bb[8], rb[8];
    if (MODE >= 1) {
        float4 t0 = *(const float4*)&bias[c0], t1 = *(const float4*)&bias[c0 + 4];
        bb[0]=t0.x; bb[1]=t0.y; bb[2]=t0.z; bb[3]=t0.w;
        bb[4]=t1.x; bb[5]=t1.y; bb[6]=t1.z; bb[7]=t1.w;
    }
    if (MODE == 2) {
        float4 t0 = *(const float4*)&resb[c0], t1 = *(const float4*)&resb[c0 + 4];
        rb[0]=t0.x; rb[1]=t0.y; rb[2]=t0.z; rb[3]=t0.w;
        rb[4]=t1.x; rb[5]=t1.y; rb[6]=t1.z; rb[7]=t1.w;
    }
#pragma unroll
    for (int i = 0; i < 8; i++) {
        int row = m0 + r0 + i;
        float v[8];
#pragma unroll
        for (int j = 0; j < 4; j++) {
            float2 f = upk2(acc[i][j]);
            v[2 * j] = f.x; v[2 * j + 1] = f.y;
        }
        if (MODE == 0) {
            if (dophi) {
#pragma unroll
                for (int x = 0; x < 8; x++) v[x] = phif(v[x]);
            }
        } else if (MODE == 1) {
#pragma unroll
            for (int x = 0; x < 8; x++) v[x] = fmaxf(v[x] + bb[x], 0.f);
        } else {
            float4 q0 = *(const float4*)&res[(size_t)row * DD + c0];
            float4 q1 = *(const float4*)&res[(size_t)row * DD + c0 + 4];
            float rr[8] = {q0.x, q0.y, q0.z, q0.w, q1.x, q1.y, q1.z, q1.w};
#pragma unroll
            for (int x = 0; x < 8; x++) v[x] = fmaxf(v[x] + bb[x], 0.f) + rr[x] + rb[x];
        }
        *(float4*)(C + (size_t)row * DD + c0)     = make_float4(v[0], v[1], v[2], v[3]);
        *(float4*)(C + (size_t)row * DD + c0 + 4) = make_float4(v[4], v[5], v[6], v[7]);
    }
}

// ---------------- 3) per-chunk KV outer-product sums + K sums (8x8) ---------
__global__ __launch_bounds__(256) void chunksum_kernel() {
    __shared__ float sK[CH][DD];
    __shared__ float sV[CH][DD];
    int tid = threadIdx.x;
    int chunk = blockIdx.x;
    int base = chunk * CH;
    int lr = tid >> 3, lc = (tid & 7) * 16;
#pragma unroll
    for (int j = 0; j < 4; j++) {
        *(float4*)&sK[lr][lc + 4 * j] = *(const float4*)&gK[(size_t)(base + lr) * DD + lc + 4 * j];
        *(float4*)&sV[lr][lc + 4 * j] = *(const float4*)&gV[(size_t)(base + lr) * DD + lc + 4 * j];
    }
    __syncthreads();

    int r0 = (tid >> 4) * 8;
    int c0 = (tid & 15) * 8;
    u64 acc[8][4];
#pragma unroll
    for (int i = 0; i < 8; i++)
#pragma unroll
        for (int j = 0; j < 4; j++) acc[i][j] = 0ull;

#pragma unroll 4
    for (int t = 0; t < CH; t++) {
        float4 kf0 = *(const float4*)&sK[t][r0];
        float4 kf1 = *(const float4*)&sK[t][r0 + 4];
        ulonglong2 v01 = *(const ulonglong2*)&sV[t][c0];
        ulonglong2 v23 = *(const ulonglong2*)&sV[t][c0 + 4];
        float kr[8] = {kf0.x, kf0.y, kf0.z, kf0.w, kf1.x, kf1.y, kf1.z, kf1.w};
#pragma unroll
        for (int i = 0; i < 8; i++) {
            u64 aa = pkdup(kr[i]);
            fma2(acc[i][0], aa, v01.x);
            fma2(acc[i][1], aa, v01.y);
            fma2(acc[i][2], aa, v23.x);
            fma2(acc[i][3], aa, v23.y);
        }
    }
    float* dst = gSprev + (size_t)chunk * DD * DD;
#pragma unroll
    for (int i = 0; i < 8; i++) {
        float2 f0 = upk2(acc[i][0]), f1 = upk2(acc[i][1]);
        float2 f2 = upk2(acc[i][2]), f3 = upk2(acc[i][3]);
        *(float4*)&dst[(r0 + i) * DD + c0]     = make_float4(f0.x, f0.y, f1.x, f1.y);
        *(float4*)&dst[(r0 + i) * DD + c0 + 4] = make_float4(f2.x, f2.y, f3.x, f3.y);
    }
    if (tid < DD) {
        float s = 0.f;
#pragma unroll 8
        for (int t = 0; t < CH; t++) s += sK[t][tid];
        gZprev[chunk * DD + tid] = s;
    }
}

// ---------------- 4) merged exclusive inter-chunk scans ---------------------
__global__ __launch_bounds__(256) void scan_kernel(const float* __restrict__ S0,
                                                   const float* __restrict__ Z0) {
    if (blockIdx.y < 4) {
        int e = blockIdx.x * 256 + threadIdx.x;
        int b = blockIdx.y;
        float run = S0[(size_t)b * 16384 + e];
#pragma unroll 8
        for (int c = 0; c < NC_B; c++) {
            size_t idx = ((size_t)(b * NC_B + c)) * 16384 + e;
            float v = gSprev[idx];
            gSprev[idx] = run;
            run += v;
        }
    } else if (blockIdx.x < 4 && threadIdx.x < DD) {
        int d = threadIdx.x;
        int b = blockIdx.x;
        float run = Z0[b * DD + d];
#pragma unroll 8
        for (int c = 0; c < NC_B; c++) {
            size_t idx = (size_t)(b * NC_B + c) * DD + d;
            float v = gZprev[idx];
            gZprev[idx] = run;
            run += v;
        }
    }
}

// ---------------- 5) fused S-writer + attention-output kernel ---------------
// even blockIdx -> S-writer for chunk bx/2, odd -> attn for chunk bx/2.
struct SwSM { float k[CH][DD]; float v[CH][DD]; };
struct AtSM {
    float q[CH][DD + 4];
    float kv[CH][DD + 4];
    float a[CH][CH + 2];
    float sp[16][DD];
    float row[CH];
    float zp[DD];
};
union FusedSM { SwSM sw; AtSM at; };

__global__ __launch_bounds__(512, 2) void swattn_kernel(float* __restrict__ Sout,
                                                        float* __restrict__ Zout) {
    __shared__ FusedSM sm;
    int tid = threadIdx.x;
    int chunk = blockIdx.x >> 1;
    int base = chunk * CH;

    if ((blockIdx.x & 1) == 0) {
        // ---------------- S writer ----------------
        SwSM& sw = sm.sw;
        int lr = tid >> 4, lc = (tid & 15) * 8;
        *(float4*)&sw.k[lr][lc]     = *(const float4*)&gK[(size_t)(base + lr) * DD + lc];
        *(float4*)&sw.k[lr][lc + 4] = *(const float4*)&gK[(size_t)(base + lr) * DD + lc + 4];
        *(float4*)&sw.v[lr][lc]     = *(const float4*)&gV[(size_t)(base + lr) * DD + lc];
        *(float4*)&sw.v[lr][lc + 4] = *(const float4*)&gV[(size_t)(base + lr) * DD + lc + 4];

        int r0 = (tid >> 4) * 4;
        int c0 = (tid & 15) * 8;
        const float* Sp = gSprev + (size_t)chunk * DD * DD;
        u64 acc[4][4];
#pragma unroll
        for (int i = 0; i < 4; i++) {
            float4 f0 = *(const float4*)&Sp[(r0 + i) * DD + c0];
            float4 f1 = *(const float4*)&Sp[(r0 + i) * DD + c0 + 4];
            acc[i][0] = pk2(f0.x, f0.y); acc[i][1] = pk2(f0.z, f0.w);
            acc[i][2] = pk2(f1.x, f1.y); acc[i][3] = pk2(f1.z, f1.w);
        }
        __syncthreads();

        for (int t = 0; t < CH; t++) {
            float4 kv = *(const float4*)&sw.k[t][r0];
            ulonglong2 v01 = *(const ulonglong2*)&sw.v[t][c0];
            ulonglong2 v23 = *(const ulonglong2*)&sw.v[t][c0 + 4];
            float kr[4] = {kv.x, kv.y, kv.z, kv.w};
            float* drow = Sout + (size_t)(base + t) * 16384;
#pragma unroll
            for (int i = 0; i < 4; i++) {
                u64 aa = pkdup(kr[i]);
                fma2(acc[i][0], aa, v01.x);
                fma2(acc[i][1], aa, v01.y);
                fma2(acc[i][2], aa, v23.x);
                fma2(acc[i][3], aa, v23.y);
                float2 f0 = upk2(acc[i][0]), f1 = upk2(acc[i][1]);
                float2 f2 = upk2(acc[i][2]), f3 = upk2(acc[i][3]);
                *(float4*)&drow[(r0 + i) * DD + c0]     = make_float4(f0.x, f0.y, f1.x, f1.y);
                *(float4*)&drow[(r0 + i) * DD + c0 + 4] = make_float4(f2.x, f2.y, f3.x, f3.y);
            }
        }
    } else {
        // ---------------- attention output + Z ----------------
        AtSM& at = sm.at;
        int lr = tid >> 4, lc = (tid & 15) * 8;
        *(float4*)&at.q[lr][lc]      = *(const float4*)&gQ[(size_t)(base + lr) * DD + lc];
        *(float4*)&at.q[lr][lc + 4]  = *(const float4*)&gQ[(size_t)(base + lr) * DD + lc + 4];
        *(float4*)&at.kv[lr][lc]     = *(const float4*)&gK[(size_t)(base + lr) * DD + lc];
        *(float4*)&at.kv[lr][lc + 4] = *(const float4*)&gK[(size_t)(base + lr) * DD + lc + 4];
        if (tid < DD) at.zp[tid] = gZprev[chunk * DD + tid];
        __syncthreads();

        // Phase A: masked QK^T (each thread 2 elems)
        {
            int tq = tid >> 4;
            int tk = (tid & 15) * 2;
            u64 a2[2] = {0ull, 0ull};
#pragma unroll 8
            for (int dd = 0; dd < 64; dd++) {
                u64 qp  = *(const u64*)&at.q[tq][2 * dd];
                u64 kp0 = *(const u64*)&at.kv[tk][2 * dd];
                u64 kp1 = *(const u64*)&at.kv[tk + 1][2 * dd];
                fma2(a2[0], qp, kp0);
                fma2(a2[1], qp, kp1);
            }
#pragma unroll
            for (int j = 0; j < 2; j++) {
                float2 f = upk2(a2[j]);
                at.a[tq][tk + j] = (tk + j <= tq) ? (f.x + f.y) : 0.0f;
            }
        }

        // Z output (sm.at.kv still holds K)
        if (tid < DD) {
            float zacc = at.zp[tid];
#pragma unroll 4
            for (int t = 0; t < CH; t++) {
                zacc += at.kv[t][tid];
                Zout[(size_t)(base + t) * DD + tid] = zacc;
            }
        }
        __syncthreads();

        // denominators
        if (tid < CH) {
            float s = 1e-5f;
#pragma unroll 8
            for (int c = 0; c < CH; c++) s += at.a[tid][c];
            float qz = 0.f;
#pragma unroll 8
            for (int d = 0; d < DD; d++) qz += at.q[tid][d] * at.zp[d];
            at.row[tid] = s + qz;
        }
        __syncthreads();

        // overwrite kv with V
        *(float4*)&at.kv[lr][lc]     = *(const float4*)&gV[(size_t)(base + lr) * DD + lc];
        *(float4*)&at.kv[lr][lc + 4] = *(const float4*)&gV[(size_t)(base + lr) * DD + lc + 4];

        int r0 = tid >> 4;            // 1 row per thread (32 rows)
        int c0 = (tid & 15) * 8;      // 8 cols
        u64 acc[4] = {0ull, 0ull, 0ull, 0ull};

        // Phase C: Q @ Sprev in 8 d-tiles of 16
        const float* Sp = gSprev + (size_t)chunk * DD * DD;
        int spr = tid >> 5, spc = (tid & 31) * 4;
        for (int dt = 0; dt < 8; dt++) {
            __syncthreads();
            *(float4*)&at.sp[spr][spc] = *(const float4*)&Sp[(dt * 16 + spr) * DD + spc];
            __syncthreads();
#pragma unroll
            for (int d = 0; d < 16; d++) {
                u64 aa = pkdup(at.q[r0][dt * 16 + d]);
                ulonglong2 s01 = *(const ulonglong2*)&at.sp[d][c0];
                ulonglong2 s23 = *(const ulonglong2*)&at.sp[d][c0 + 4];
                fma2(acc[0], aa, s01.x); fma2(acc[1], aa, s01.y);
                fma2(acc[2], aa, s23.x); fma2(acc[3], aa, s23.y);
            }
        }
        __syncthreads();

        // Phase B: masked A @ V
#pragma unroll 4
        for (int t = 0; t < CH; t++) {
            u64 aa = pkdup(at.a[r0][t]);
            ulonglong2 v01 = *(const ulonglong2*)&at.kv[t][c0];
            ulonglong2 v23 = *(const ulonglong2*)&at.kv[t][c0 + 4];
            fma2(acc[0], aa, v01.x); fma2(acc[1], aa, v01.y);
            fma2(acc[2], aa, v23.x); fma2(acc[3], aa, v23.y);
        }

        float rd = 1.0f / at.row[r0];
        float2 f0 = upk2(acc[0]), f1 = upk2(acc[1]);
        float2 f2 = upk2(acc[2]), f3 = upk2(acc[3]);
        float* dst = gP + (size_t)(base + r0) * DD + c0;
        *(float4*)dst       = make_float4(f0.x * rd, f0.y * rd, f1.x * rd, f1.y * rd);
        *(float4*)(dst + 4) = make_float4(f2.x * rd, f2.y * rd, f3.x * rd, f3.y * rd);
    }
}

// ---------------- launch ------------------------------------------------------
extern "C" void kernel_launch(void* const* d_in, const int* in_sizes, int n_in,
                              void* d_out, int out_size) {
    const float* history = (const float*)d_in[0];
    const float* S0   = (const float*)d_in[1];
    const float* Z0   = (const float*)d_in[2];
    const float* Wk   = (const float*)d_in[3];
    const float* Wq   = (const float*)d_in[4];
    const float* Wv   = (const float*)d_in[5];
    const float* ln_g = (const float*)d_in[6];
    const float* ln_b = (const float*)d_in[7];
    const float* w1   = (const float*)d_in[8];
    const float* b1   = (const float*)d_in[9];
    const float* w2   = (const float*)d_in[10];
    const float* b2   = (const float*)d_in[11];
    const float* sc_w = (const float*)d_in[12];
    const float* sc_b = (const float*)d_in[13];

    float* outO = (float*)d_out;
    float* outS = outO + (size_t)R_TOT * DD;
    float* outZ = outS + (size_t)R_TOT * DD * DD;

    float *pX, *pK, *pQ, *pV, *pSC, *pP, *pH;
    cudaGetSymbolAddress((void**)&pX,  gX);
    cudaGetSymbolAddress((void**)&pK,  gK);
    cudaGetSymbolAddress((void**)&pQ,  gQ);
    cudaGetSymbolAddress((void**)&pV,  gV);
    cudaGetSymbolAddress((void**)&pSC, gSC);
    cudaGetSymbolAddress((void**)&pP,  gP);
    cudaGetSymbolAddress((void**)&pH,  gH);

    // 1) LayerNorm
    ln_kernel<<<R_TOT, 128>>>(history, ln_g, ln_b);
    // 2) all four projections in one launch (phi on K,Q)
    gemm_kernel<FIN, 0><<<dim3(64, 4), 256>>>(pX, Wk, Wq, Wv, sc_w,
                                              pK, pQ, pV, pSC,
                                              nullptr, nullptr, nullptr);
    // 3) chunk sums
    chunksum_kernel<<<NCHUNK, 256>>>();
    // 4) merged exclusive scans (+S0/+Z0 folded)
    scan_kernel<<<dim3(64, 5), 256>>>(S0, Z0);
    // 5) fused S-stream writer + attention output + Z output
    swattn_kernel<<<2 * NCHUNK, 512>>>(outS, outZ);
    // 6) FF1: relu(P@w1 + b1)
    gemm_kernel<DD, 1><<<dim3(64, 1), 256>>>(pP, w1, nullptr, nullptr, nullptr,
                                             pH, nullptr, nullptr, nullptr,
                                             b1, nullptr, nullptr);
    // 7) FF2: relu(H@w2 + b2) + SC + sc_b
    gemm_kernel<DD, 2><<<dim3(64, 1), 256>>>(pH, w2, nullptr, nullptr, nullptr,
                                             outO, nullptr, nullptr, nullptr,
                                             b2, pSC, sc_b);
}